// round 15
// baseline (speedup 1.0000x reference)
#include <cuda_runtime.h>
#include <cstdint>

#define A_TOT 1445
#define NBLK 4096
#define BLOCK 128
#define NITER 12            // ceil(1445 / 128)
#define BUFCAP 256

__device__ float g_partial[3 * NBLK];
__device__ int g_done = 0;

__device__ __forceinline__ void tf_round(uint32_t &x0, uint32_t &x1, int r) {
    x0 += x1;
    x1 = __funnelshift_l(x1, x1, r);
    x1 ^= x0;
}

// JAX threefry2x32 (20 rounds)
__device__ __forceinline__ uint2 threefry2x32(uint32_t k0, uint32_t k1, uint32_t x0, uint32_t x1) {
    uint32_t k2 = k0 ^ k1 ^ 0x1BD11BDAu;
    x0 += k0; x1 += k1;
    tf_round(x0,x1,13); tf_round(x0,x1,15); tf_round(x0,x1,26); tf_round(x0,x1,6);
    x0 += k1; x1 += k2 + 1u;
    tf_round(x0,x1,17); tf_round(x0,x1,29); tf_round(x0,x1,16); tf_round(x0,x1,24);
    x0 += k2; x1 += k0 + 2u;
    tf_round(x0,x1,13); tf_round(x0,x1,15); tf_round(x0,x1,26); tf_round(x0,x1,6);
    x0 += k0; x1 += k1 + 3u;
    tf_round(x0,x1,17); tf_round(x0,x1,29); tf_round(x0,x1,16); tf_round(x0,x1,24);
    x0 += k1; x1 += k2 + 4u;
    tf_round(x0,x1,13); tf_round(x0,x1,15); tf_round(x0,x1,26); tf_round(x0,x1,6);
    x0 += k2; x1 += k0 + 5u;
    return make_uint2(x0, x1);
}

// two independent counters under the SAME key, interleaved for ILP
__device__ __forceinline__ void threefry2x32_pair_samekey(
    uint32_t k0, uint32_t k1, uint32_t xa, uint32_t xb,
    uint32_t &oa, uint32_t &ob)
{
    uint32_t k2 = k0 ^ k1 ^ 0x1BD11BDAu;
    uint32_t a0 = k0, a1 = xa + k1;
    uint32_t b0 = k0, b1 = xb + k1;
    #define TFP(r) { a0 += a1; a1 = __funnelshift_l(a1,a1,r); a1 ^= a0; \
                     b0 += b1; b1 = __funnelshift_l(b1,b1,r); b1 ^= b0; }
    TFP(13) TFP(15) TFP(26) TFP(6)
    a0 += k1; a1 += k2 + 1u;  b0 += k1; b1 += k2 + 1u;
    TFP(17) TFP(29) TFP(16) TFP(24)
    a0 += k2; a1 += k0 + 2u;  b0 += k2; b1 += k0 + 2u;
    TFP(13) TFP(15) TFP(26) TFP(6)
    a0 += k0; a1 += k1 + 3u;  b0 += k0; b1 += k1 + 3u;
    TFP(17) TFP(29) TFP(16) TFP(24)
    a0 += k1; a1 += k2 + 4u;  b0 += k1; b1 += k2 + 4u;
    TFP(13) TFP(15) TFP(26) TFP(6)
    a0 += k2; a1 += k0 + 5u;  b0 += k2; b1 += k0 + 5u;
    #undef TFP
    oa = a0 ^ a1;
    ob = b0 ^ b1;
}

__device__ __forceinline__ float softplus_f(float x) {
    return fmaxf(x, 0.0f) + log1pf(expf(-fabsf(x)));
}

__device__ __forceinline__ float warpReduceSum(float v) {
    #pragma unroll
    for (int o = 16; o > 0; o >>= 1) v += __shfl_down_sync(0xffffffffu, v, o);
    return v;
}

__global__ __launch_bounds__(BLOCK, 14) void rpn_sample_kernel(
    const float* __restrict__ pred_cls,
    const float* __restrict__ pred_reg,
    const float* __restrict__ gt_bbox,
    const float* __restrict__ anchor_center,
    const float* __restrict__ anchor_corner,
    float* __restrict__ out)
{
    __shared__ float s_cls[A_TOT];             // logits; reused as reduce scratch at end
    __shared__ uint32_t s_key[A_TOT];          // 23-bit uniform key (bits >> 9)
    __shared__ int s_hist[256];
    __shared__ unsigned long long s_buf[BUFCAP];
    __shared__ int s_cnt[4];                   // npos, nneg, acc, bufcnt
    __shared__ float s_regsum;
    __shared__ float s_clssum;
    __shared__ uint32_t s_thrkP, s_thriP;      // pos threshold: key + index
    __shared__ int s_bin, s_cumb;

    const int n = blockIdx.x;
    const int tid = threadIdx.x;

    // zero histogram + control state before any use
    s_hist[tid] = 0;
    s_hist[tid + BLOCK] = 0;
    if (tid == 0) {
        s_regsum = 0.f; s_clssum = 0.f;
        s_cnt[0] = s_cnt[1] = s_cnt[2] = s_cnt[3] = 0;
        s_thrkP = 0xFFFFFFFFu; s_thriP = 0xFFFFFFFFu;
    }

    // neg-stream key only (pos keys needed only if npos > 16 — computed lazily)
    uint32_t kn0, kn1;
    {
        uint2 kn = threefry2x32(0u, 42u, 0u, (uint32_t)(NBLK + n));
        kn0 = kn.x; kn1 = kn.y;
    }
    __syncthreads();   // hist/cnt zero visible before fused-loop atomics

    const float4 gt = __ldg(((const float4*)gt_bbox) + n);
    const float ga = __fmul_rn(__fsub_rn(gt.z, gt.x), __fsub_rn(gt.w, gt.y));
    const float gcx = (gt.x + gt.z) * 0.5f;
    const float gcy = (gt.y + gt.w) * 0.5f;
    const float gw = gt.z - gt.x, gh = gt.w - gt.y;

    const float* pc = pred_cls + (size_t)n * A_TOT;
    const float* prg = pred_reg + (size_t)n * 4 * A_TOT;

    int lcnt = 0;          // packed per-warp: lpos<<20 | lneg<<10 | lacc
    float lreg = 0.f;
    uint32_t mbits = 0;    // 2 bits per j: this thread's anchor masks

    // ---- fused loop: loads -> cipher (in load shadow) -> IoU -> hist ----
    for (int t = 0; t < 6; t++) {
        const int j1 = 2 * t, j2 = 2 * t + 1;
        const int i1 = tid + j1 * BLOCK;
        const int i2 = tid + j2 * BLOCK;
        const bool v2 = (i2 < A_TOT);   // only last pair is partial (i1 always valid)

        // issue loads first — consumed after the cipher
        float4 ac1 = __ldg(((const float4*)anchor_corner) + i1);
        float4 ac2 = __ldg(((const float4*)anchor_corner) + (v2 ? i2 : i1));
        float c1 = __ldg(pc + i1);
        float c2 = __ldg(pc + (v2 ? i2 : i1));

        // ~100 ALU instructions fill the load latency shadow
        uint32_t ya, yb;
        threefry2x32_pair_samekey(kn0, kn1, (uint32_t)i1, (uint32_t)i2, ya, yb);
        uint32_t ka = ya >> 9, kb = yb >> 9;
        s_key[i1] = ka;
        if (v2) s_key[i2] = kb;

        // IoU + mask, anchor 1
        {
            float ltx = fmaxf(gt.x, ac1.x), lty = fmaxf(gt.y, ac1.y);
            float rbx = fminf(gt.z, ac1.z), rby = fminf(gt.w, ac1.w);
            float w = fmaxf(__fsub_rn(rbx, ltx), 0.f);
            float h = fmaxf(__fsub_rn(rby, lty), 0.f);
            float inter = __fmul_rn(w, h);
            float ab = __fmul_rn(__fsub_rn(ac1.z, ac1.x), __fsub_rn(ac1.w, ac1.y));
            float uni = __fsub_rn(__fadd_rn(ga, ab), inter);
            float iou = __fdiv_rn(inter, uni);
            int m = (iou > 0.6f) ? 1 : ((iou < 0.3f) ? 0 : 2);
            mbits |= (uint32_t)m << (2 * j1);
            s_cls[i1] = c1;
            bool pos = (m == 1);
            lcnt += ((c1 >= 0.6f) == pos) ? 1 : 0;
            lcnt += pos ? 0x100000 : ((m == 0) ? 0x400 : 0);
            if (m == 0) atomicAdd(&s_hist[ka >> 15], 1);
            if (pos) {
                float4 ce = __ldg(((const float4*)anchor_center) + i1);
                float t0 = (gcx - ce.x) / ce.z;
                float t1 = (gcy - ce.y) / ce.w;
                float t2 = logf(gw / ce.z);
                float t3 = logf(gh / ce.w);
                float d0 = prg[i1]             - t0;
                float d1 = prg[A_TOT + i1]     - t1;
                float d2 = prg[2 * A_TOT + i1] - t2;
                float d3 = prg[3 * A_TOT + i1] - t3;
                lreg += d0 * d0 + d1 * d1 + d2 * d2 + d3 * d3;
            }
        }

        // IoU + mask, anchor 2
        if (v2) {
            float ltx = fmaxf(gt.x, ac2.x), lty = fmaxf(gt.y, ac2.y);
            float rbx = fminf(gt.z, ac2.z), rby = fminf(gt.w, ac2.w);
            float w = fmaxf(__fsub_rn(rbx, ltx), 0.f);
            float h = fmaxf(__fsub_rn(rby, lty), 0.f);
            float inter = __fmul_rn(w, h);
            float ab = __fmul_rn(__fsub_rn(ac2.z, ac2.x), __fsub_rn(ac2.w, ac2.y));
            float uni = __fsub_rn(__fadd_rn(ga, ab), inter);
            float iou = __fdiv_rn(inter, uni);
            int m = (iou > 0.6f) ? 1 : ((iou < 0.3f) ? 0 : 2);
            mbits |= (uint32_t)m << (2 * j2);
            s_cls[i2] = c2;
            bool pos = (m == 1);
            lcnt += ((c2 >= 0.6f) == pos) ? 1 : 0;
            lcnt += pos ? 0x100000 : ((m == 0) ? 0x400 : 0);
            if (m == 0) atomicAdd(&s_hist[kb >> 15], 1);
            if (pos) {
                float4 ce = __ldg(((const float4*)anchor_center) + i2);
                float t0 = (gcx - ce.x) / ce.z;
                float t1 = (gcy - ce.y) / ce.w;
                float t2 = logf(gw / ce.z);
                float t3 = logf(gh / ce.w);
                float d0 = prg[i2]             - t0;
                float d1 = prg[A_TOT + i2]     - t1;
                float d2 = prg[2 * A_TOT + i2] - t2;
                float d3 = prg[3 * A_TOT + i2] - t3;
                lreg += d0 * d0 + d1 * d1 + d2 * d2 + d3 * d3;
            }
        }
    }

    // warp-level packed sum is safe (<= 384 per field); unpack before block atomics
    lcnt = (int)__reduce_add_sync(0xffffffffu, (unsigned)lcnt);
    lreg = warpReduceSum(lreg);
    if ((tid & 31) == 0) {
        atomicAdd(&s_cnt[0], lcnt >> 20);
        atomicAdd(&s_cnt[1], (lcnt >> 10) & 0x3FF);
        atomicAdd(&s_cnt[2], lcnt & 0x3FF);
        atomicAdd(&s_regsum, lreg);
    }
    __syncthreads();

    const int npos = s_cnt[0], nneg = s_cnt[1], naccc = s_cnt[2];
    const int k_p = min(npos, 16);
    const int k_n = min(nneg, (npos > 0) ? 3 * npos : 48);

    // ---- positive threshold (rare: npos > 16): lazily compute kp ciphers ----
    if (npos > k_p) {
        uint32_t kp0, kp1;
        {
            uint2 kp = threefry2x32(0u, 42u, 0u, (uint32_t)n);
            kp0 = kp.x; kp1 = kp.y;
        }
        if (tid == 0) s_cnt[3] = 0;
        __syncthreads();
        #pragma unroll
        for (int j = 0; j < NITER; j++) {
            int i = tid + j * BLOCK;
            if (i < A_TOT && ((mbits >> (2 * j)) & 3) == 1) {
                uint2 y = threefry2x32(kp0, kp1, 0u, (uint32_t)i);
                uint32_t key = (y.x ^ y.y) >> 9;
                s_key[i] = key;   // pos entries now carry kp keys
                int p = atomicAdd(&s_cnt[3], 1);
                if (p < BUFCAP) s_buf[p] = (((unsigned long long)key) << 16) | (unsigned)i;
            }
        }
        __syncthreads();
        int m = min(s_cnt[3], BUFCAP);
        for (int t = tid; t < m; t += BLOCK) {
            unsigned long long me = s_buf[t];
            int cnt = 0;
            for (int q = 0; q < m; q++) cnt += (s_buf[q] < me) ? 1 : 0;
            if (cnt == k_p - 1) {
                s_thrkP = (uint32_t)(me >> 16);
                s_thriP = (uint32_t)(me & 0xFFFFu);
            }
        }
        __syncthreads();
        if (tid == 0) s_cnt[3] = 0;
        __syncthreads();
    }

    // ---- negative bin: histogram scan (bin = 256 when all negs selected) ----
    if (nneg > k_n) {
        if (tid < 32) {
            int base = tid * 8;
            int h[8];
            int lsum = 0;
            #pragma unroll
            for (int j = 0; j < 8; j++) { h[j] = s_hist[base + j]; lsum += h[j]; }
            int incl = lsum;
            #pragma unroll
            for (int o = 1; o < 32; o <<= 1) {
                int t = __shfl_up_sync(0xffffffffu, incl, o);
                if (tid >= o) incl += t;
            }
            int run = incl - lsum;
            #pragma unroll
            for (int j = 0; j < 8; j++) {
                int nrun = run + h[j];
                if (run < k_n && k_n <= nrun) { s_bin = base + j; s_cumb = run; }
                run = nrun;
            }
        }
    } else if (tid == 0) {
        s_bin = 256;   // every 8-bit bin value is < 256 -> all negs selected
        s_cumb = k_n;  // jrank = 0, buffer stays empty
    }
    __syncthreads();
    const int bin = s_bin;
    const int jrank = k_n - s_cumb;   // in-bin selection count
    const uint32_t thrkP = s_thrkP, thriP = s_thriP;

    // ---- MERGED pass: selected BCE + boundary-bin collection ----
    float lcls = 0.f;
    #pragma unroll
    for (int j = 0; j < NITER; j++) {
        int i = tid + j * BLOCK;
        if (i >= A_TOT) break;
        int m = (mbits >> (2 * j)) & 3;
        if (m == 2) continue;
        uint32_t key = s_key[i];
        if (m == 1) {
            bool sel = (key < thrkP) || ((key == thrkP) && ((uint32_t)i <= thriP));
            if (sel) lcls += softplus_f(-s_cls[i]);
        } else {
            int b = (int)(key >> 15);
            if (b < bin) {
                lcls += softplus_f(s_cls[i]);
            } else if (b == bin) {
                int p = atomicAdd(&s_cnt[3], 1);
                if (p < BUFCAP) s_buf[p] = (((unsigned long long)key) << 16) | (unsigned)i;
            }
        }
    }
    __syncthreads();

    // in-bin rank: take the jrank smallest, add their BCE directly
    {
        int mm = min(s_cnt[3], BUFCAP);
        for (int t = tid; t < mm; t += BLOCK) {
            unsigned long long me = s_buf[t];
            int cnt = 0;
            for (int q = 0; q < mm; q++) cnt += (s_buf[q] < me) ? 1 : 0;
            if (cnt < jrank) {
                int idx = (int)(me & 0xFFFFu);
                lcls += softplus_f(s_cls[idx]);
            }
        }
    }
    lcls = warpReduceSum(lcls);
    if ((tid & 31) == 0) atomicAdd(&s_clssum, lcls);
    __syncthreads();

    __shared__ bool s_last;
    if (tid == 0) {
        float denom = (float)max(k_p + k_n, 1);
        g_partial[n]            = s_clssum / denom;
        g_partial[NBLK + n]     = (npos > 0) ? (s_regsum / (4.0f * (float)npos)) : 0.0f;
        g_partial[2 * NBLK + n] = (float)naccc / (float)A_TOT;
        __threadfence();
        int prev = atomicAdd(&g_done, 1);
        s_last = (prev == NBLK - 1);
    }
    __syncthreads();

    // last block folds the final reduction — reuse s_cls as scratch (dead now)
    if (s_last) {
        float* sh0 = s_cls;            // [0, 128)
        float* sh1 = s_cls + BLOCK;    // [128, 256)
        float* sh2 = s_cls + 2*BLOCK;  // [256, 384)
        float lc = 0.f, lr = 0.f, acs = 0.f;
        for (int i = tid; i < NBLK; i += BLOCK) {
            lc  += g_partial[i];
            lr  += g_partial[NBLK + i];
            acs += g_partial[2 * NBLK + i];
        }
        __syncthreads();
        sh0[tid] = lc; sh1[tid] = lr; sh2[tid] = acs;
        __syncthreads();
        #pragma unroll
        for (int off = BLOCK / 2; off > 0; off >>= 1) {
            if (tid < off) {
                sh0[tid] += sh0[tid + off];
                sh1[tid] += sh1[tid + off];
                sh2[tid] += sh2[tid + off];
            }
            __syncthreads();
        }
        if (tid == 0) {
            float mlc = sh0[0] / (float)NBLK;
            float mlr = sh1[0] / (float)NBLK;
            float mac = sh2[0] / (float)NBLK;
            out[0] = mlc + mlr;
            out[1] = mlc;
            out[2] = mlr;
            out[3] = mac;
            g_done = 0;   // reset for next graph replay
        }
    }
}

extern "C" void kernel_launch(void* const* d_in, const int* in_sizes, int n_in,
                              void* d_out, int out_size) {
    const float* pred_cls      = (const float*)d_in[0];
    const float* pred_reg      = (const float*)d_in[1];
    const float* gt_bbox       = (const float*)d_in[2];
    const float* anchor_center = (const float*)d_in[3];
    const float* anchor_corner = (const float*)d_in[4];
    (void)in_sizes; (void)n_in; (void)out_size;

    rpn_sample_kernel<<<NBLK, BLOCK>>>(pred_cls, pred_reg, gt_bbox,
                                       anchor_center, anchor_corner,
                                       (float*)d_out);
}

// round 16
// speedup vs baseline: 1.0726x; 1.0726x over previous
#include <cuda_runtime.h>
#include <cstdint>

#define A_TOT 1445
#define NBLK 4096
#define BLOCK 128
#define NITER 12            // ceil(1445 / 128)
#define BUFCAP 256

__device__ float g_partial[3 * NBLK];
__device__ int g_done = 0;

__device__ __forceinline__ void tf_round(uint32_t &x0, uint32_t &x1, int r) {
    x0 += x1;
    x1 = __funnelshift_l(x1, x1, r);
    x1 ^= x0;
}

// JAX threefry2x32 (20 rounds)
__device__ __forceinline__ uint2 threefry2x32(uint32_t k0, uint32_t k1, uint32_t x0, uint32_t x1) {
    uint32_t k2 = k0 ^ k1 ^ 0x1BD11BDAu;
    x0 += k0; x1 += k1;
    tf_round(x0,x1,13); tf_round(x0,x1,15); tf_round(x0,x1,26); tf_round(x0,x1,6);
    x0 += k1; x1 += k2 + 1u;
    tf_round(x0,x1,17); tf_round(x0,x1,29); tf_round(x0,x1,16); tf_round(x0,x1,24);
    x0 += k2; x1 += k0 + 2u;
    tf_round(x0,x1,13); tf_round(x0,x1,15); tf_round(x0,x1,26); tf_round(x0,x1,6);
    x0 += k0; x1 += k1 + 3u;
    tf_round(x0,x1,17); tf_round(x0,x1,29); tf_round(x0,x1,16); tf_round(x0,x1,24);
    x0 += k1; x1 += k2 + 4u;
    tf_round(x0,x1,13); tf_round(x0,x1,15); tf_round(x0,x1,26); tf_round(x0,x1,6);
    x0 += k2; x1 += k0 + 5u;
    return make_uint2(x0, x1);
}

// two independent counters under the SAME key, interleaved for ILP
__device__ __forceinline__ void threefry2x32_pair_samekey(
    uint32_t k0, uint32_t k1, uint32_t xa, uint32_t xb,
    uint32_t &oa, uint32_t &ob)
{
    uint32_t k2 = k0 ^ k1 ^ 0x1BD11BDAu;
    uint32_t a0 = k0, a1 = xa + k1;
    uint32_t b0 = k0, b1 = xb + k1;
    #define TFP(r) { a0 += a1; a1 = __funnelshift_l(a1,a1,r); a1 ^= a0; \
                     b0 += b1; b1 = __funnelshift_l(b1,b1,r); b1 ^= b0; }
    TFP(13) TFP(15) TFP(26) TFP(6)
    a0 += k1; a1 += k2 + 1u;  b0 += k1; b1 += k2 + 1u;
    TFP(17) TFP(29) TFP(16) TFP(24)
    a0 += k2; a1 += k0 + 2u;  b0 += k2; b1 += k0 + 2u;
    TFP(13) TFP(15) TFP(26) TFP(6)
    a0 += k0; a1 += k1 + 3u;  b0 += k0; b1 += k1 + 3u;
    TFP(17) TFP(29) TFP(16) TFP(24)
    a0 += k1; a1 += k2 + 4u;  b0 += k1; b1 += k2 + 4u;
    TFP(13) TFP(15) TFP(26) TFP(6)
    a0 += k2; a1 += k0 + 5u;  b0 += k2; b1 += k0 + 5u;
    #undef TFP
    oa = a0 ^ a1;
    ob = b0 ^ b1;
}

__device__ __forceinline__ float softplus_f(float x) {
    return fmaxf(x, 0.0f) + log1pf(expf(-fabsf(x)));
}

__device__ __forceinline__ float warpReduceSum(float v) {
    #pragma unroll
    for (int o = 16; o > 0; o >>= 1) v += __shfl_down_sync(0xffffffffu, v, o);
    return v;
}

__global__ __launch_bounds__(BLOCK, 14) void rpn_sample_kernel(
    const float* __restrict__ pred_cls,
    const float* __restrict__ pred_reg,
    const float* __restrict__ gt_bbox,
    const float* __restrict__ anchor_center,
    const float* __restrict__ anchor_corner,
    float* __restrict__ out)
{
    __shared__ float s_cls[A_TOT];             // logits; reused as reduce scratch at end
    __shared__ uint32_t s_key[A_TOT];          // 23-bit uniform key (bits >> 9)
    __shared__ int s_hist[256];
    __shared__ unsigned long long s_buf[BUFCAP];
    __shared__ int s_cnt[4];                   // npos, nneg, acc, bufcnt
    __shared__ float s_regsum;
    __shared__ float s_clssum;
    __shared__ uint32_t s_thrk[2], s_thri[2];  // thresholds: key + index
    __shared__ int s_bin, s_cumb;

    const int n = blockIdx.x;
    const int tid = threadIdx.x;

    // zero histogram + control state before any use
    s_hist[tid] = 0;
    s_hist[tid + BLOCK] = 0;
    if (tid == 0) {
        s_regsum = 0.f; s_clssum = 0.f;
        s_cnt[0] = s_cnt[1] = s_cnt[2] = s_cnt[3] = 0;
        s_thrk[0] = 0xFFFFFFFFu; s_thri[0] = 0xFFFFFFFFu;
        s_thrk[1] = 0xFFFFFFFFu; s_thri[1] = 0xFFFFFFFFu;
    }

    // neg-stream key only (pos keys needed only if npos > 16 — computed lazily)
    uint32_t kn0, kn1;
    {
        uint2 kn = threefry2x32(0u, 42u, 0u, (uint32_t)(NBLK + n));
        kn0 = kn.x; kn1 = kn.y;
    }
    __syncthreads();   // hist/cnt zero visible before fused-loop atomics

    const float4 gt = __ldg(((const float4*)gt_bbox) + n);
    const float ga = __fmul_rn(__fsub_rn(gt.z, gt.x), __fsub_rn(gt.w, gt.y));
    const float gcx = (gt.x + gt.z) * 0.5f;
    const float gcy = (gt.y + gt.w) * 0.5f;
    const float gw = gt.z - gt.x, gh = gt.w - gt.y;

    const float* pc = pred_cls + (size_t)n * A_TOT;
    const float* prg = pred_reg + (size_t)n * 4 * A_TOT;

    int lcnt = 0;          // packed per-warp: lpos<<20 | lneg<<10 | lacc
    float lreg = 0.f;
    uint32_t mbits = 0;    // 2 bits per j: this thread's anchor masks

    // logits prefetched one pair-iteration ahead (DRAM latency > 1 cipher span)
    float c1 = __ldg(pc + tid);
    float c2 = __ldg(pc + tid + BLOCK);

    // ---- fused loop: loads -> cipher (in load shadow) -> IoU -> hist ----
    for (int t = 0; t < 6; t++) {
        const int j1 = 2 * t, j2 = 2 * t + 1;
        const int i1 = tid + j1 * BLOCK;
        const int i2 = tid + j2 * BLOCK;
        const bool v2 = (i2 < A_TOT);   // only last pair is partial (i1 always valid)

        // issue current anchor loads + NEXT pair's logit loads
        float4 ac1 = __ldg(((const float4*)anchor_corner) + i1);
        float4 ac2 = __ldg(((const float4*)anchor_corner) + (v2 ? i2 : i1));
        float c1n = 0.f, c2n = 0.f;
        if (t < 5) {
            int ni1 = i1 + 2 * BLOCK;
            int ni2 = i2 + 2 * BLOCK;
            c1n = __ldg(pc + ni1);
            c2n = __ldg(pc + (ni2 < A_TOT ? ni2 : ni1));
        }

        // ~100 ALU instructions fill the load latency shadow
        uint32_t ya, yb;
        threefry2x32_pair_samekey(kn0, kn1, (uint32_t)i1, (uint32_t)i2, ya, yb);
        uint32_t ka = ya >> 9, kb = yb >> 9;
        s_key[i1] = ka;
        if (v2) s_key[i2] = kb;

        // IoU + mask, anchor 1
        {
            float ltx = fmaxf(gt.x, ac1.x), lty = fmaxf(gt.y, ac1.y);
            float rbx = fminf(gt.z, ac1.z), rby = fminf(gt.w, ac1.w);
            float w = fmaxf(__fsub_rn(rbx, ltx), 0.f);
            float h = fmaxf(__fsub_rn(rby, lty), 0.f);
            float inter = __fmul_rn(w, h);
            float ab = __fmul_rn(__fsub_rn(ac1.z, ac1.x), __fsub_rn(ac1.w, ac1.y));
            float uni = __fsub_rn(__fadd_rn(ga, ab), inter);
            float iou = __fdiv_rn(inter, uni);
            int m = (iou > 0.6f) ? 1 : ((iou < 0.3f) ? 0 : 2);
            mbits |= (uint32_t)m << (2 * j1);
            s_cls[i1] = c1;
            bool pos = (m == 1);
            lcnt += ((c1 >= 0.6f) == pos) ? 1 : 0;
            lcnt += pos ? 0x100000 : ((m == 0) ? 0x400 : 0);
            if (m == 0) atomicAdd(&s_hist[ka >> 15], 1);
            if (pos) {
                float4 ce = __ldg(((const float4*)anchor_center) + i1);
                float t0 = (gcx - ce.x) / ce.z;
                float t1 = (gcy - ce.y) / ce.w;
                float t2 = logf(gw / ce.z);
                float t3 = logf(gh / ce.w);
                float d0 = prg[i1]             - t0;
                float d1 = prg[A_TOT + i1]     - t1;
                float d2 = prg[2 * A_TOT + i1] - t2;
                float d3 = prg[3 * A_TOT + i1] - t3;
                lreg += d0 * d0 + d1 * d1 + d2 * d2 + d3 * d3;
            }
        }

        // IoU + mask, anchor 2
        if (v2) {
            float ltx = fmaxf(gt.x, ac2.x), lty = fmaxf(gt.y, ac2.y);
            float rbx = fminf(gt.z, ac2.z), rby = fminf(gt.w, ac2.w);
            float w = fmaxf(__fsub_rn(rbx, ltx), 0.f);
            float h = fmaxf(__fsub_rn(rby, lty), 0.f);
            float inter = __fmul_rn(w, h);
            float ab = __fmul_rn(__fsub_rn(ac2.z, ac2.x), __fsub_rn(ac2.w, ac2.y));
            float uni = __fsub_rn(__fadd_rn(ga, ab), inter);
            float iou = __fdiv_rn(inter, uni);
            int m = (iou > 0.6f) ? 1 : ((iou < 0.3f) ? 0 : 2);
            mbits |= (uint32_t)m << (2 * j2);
            s_cls[i2] = c2;
            bool pos = (m == 1);
            lcnt += ((c2 >= 0.6f) == pos) ? 1 : 0;
            lcnt += pos ? 0x100000 : ((m == 0) ? 0x400 : 0);
            if (m == 0) atomicAdd(&s_hist[kb >> 15], 1);
            if (pos) {
                float4 ce = __ldg(((const float4*)anchor_center) + i2);
                float t0 = (gcx - ce.x) / ce.z;
                float t1 = (gcy - ce.y) / ce.w;
                float t2 = logf(gw / ce.z);
                float t3 = logf(gh / ce.w);
                float d0 = prg[i2]             - t0;
                float d1 = prg[A_TOT + i2]     - t1;
                float d2 = prg[2 * A_TOT + i2] - t2;
                float d3 = prg[3 * A_TOT + i2] - t3;
                lreg += d0 * d0 + d1 * d1 + d2 * d2 + d3 * d3;
            }
        }

        c1 = c1n;
        c2 = c2n;
    }

    // warp-level packed sum is safe (<= 384 per field); unpack before block atomics
    lcnt = (int)__reduce_add_sync(0xffffffffu, (unsigned)lcnt);
    lreg = warpReduceSum(lreg);
    if ((tid & 31) == 0) {
        atomicAdd(&s_cnt[0], lcnt >> 20);
        atomicAdd(&s_cnt[1], (lcnt >> 10) & 0x3FF);
        atomicAdd(&s_cnt[2], lcnt & 0x3FF);
        atomicAdd(&s_regsum, lreg);
    }
    __syncthreads();

    const int npos = s_cnt[0], nneg = s_cnt[1], naccc = s_cnt[2];
    const int k_p = min(npos, 16);
    const int k_n = min(nneg, (npos > 0) ? 3 * npos : 48);

    // ---- positive threshold (rare: npos > 16): lazily compute kp ciphers ----
    if (npos > k_p) {
        uint32_t kp0, kp1;
        {
            uint2 kp = threefry2x32(0u, 42u, 0u, (uint32_t)n);
            kp0 = kp.x; kp1 = kp.y;
        }
        if (tid == 0) s_cnt[3] = 0;
        __syncthreads();
        #pragma unroll
        for (int j = 0; j < NITER; j++) {
            int i = tid + j * BLOCK;
            if (i < A_TOT && ((mbits >> (2 * j)) & 3) == 1) {
                uint2 y = threefry2x32(kp0, kp1, 0u, (uint32_t)i);
                uint32_t key = (y.x ^ y.y) >> 9;
                s_key[i] = key;   // pos entries now carry kp keys
                int p = atomicAdd(&s_cnt[3], 1);
                if (p < BUFCAP) s_buf[p] = (((unsigned long long)key) << 16) | (unsigned)i;
            }
        }
        __syncthreads();
        int m = min(s_cnt[3], BUFCAP);
        for (int t = tid; t < m; t += BLOCK) {
            unsigned long long me = s_buf[t];
            int cnt = 0;
            for (int q = 0; q < m; q++) cnt += (s_buf[q] < me) ? 1 : 0;
            if (cnt == k_p - 1) {
                s_thrk[0] = (uint32_t)(me >> 16);
                s_thri[0] = (uint32_t)(me & 0xFFFFu);
            }
        }
        __syncthreads();
        if (tid == 0) s_cnt[3] = 0;
        __syncthreads();
    }

    // ---- negative threshold: histogram scan + in-bin rank ----
    if (nneg > k_n) {
        if (tid < 32) {
            int base = tid * 8;
            int h[8];
            int lsum = 0;
            #pragma unroll
            for (int j = 0; j < 8; j++) { h[j] = s_hist[base + j]; lsum += h[j]; }
            int incl = lsum;
            #pragma unroll
            for (int o = 1; o < 32; o <<= 1) {
                int t = __shfl_up_sync(0xffffffffu, incl, o);
                if (tid >= o) incl += t;
            }
            int run = incl - lsum;
            #pragma unroll
            for (int j = 0; j < 8; j++) {
                int nrun = run + h[j];
                if (run < k_n && k_n <= nrun) { s_bin = base + j; s_cumb = run; }
                run = nrun;
            }
        }
        __syncthreads();
        const int bin = s_bin, cumb = s_cumb;
        #pragma unroll
        for (int j = 0; j < NITER; j++) {
            int i = tid + j * BLOCK;
            if (i < A_TOT && ((mbits >> (2 * j)) & 3) == 0) {
                uint32_t key = s_key[i];
                if ((int)(key >> 15) == bin) {
                    int p = atomicAdd(&s_cnt[3], 1);
                    if (p < BUFCAP) s_buf[p] = (((unsigned long long)key) << 16) | (unsigned)i;
                }
            }
        }
        __syncthreads();
        int m = min(s_cnt[3], BUFCAP);
        int j = k_n - cumb;   // 1-indexed rank within bin
        for (int t = tid; t < m; t += BLOCK) {
            unsigned long long me = s_buf[t];
            int cnt = 0;
            for (int q = 0; q < m; q++) cnt += (s_buf[q] < me) ? 1 : 0;
            if (cnt == j - 1) {
                s_thrk[1] = (uint32_t)(me >> 16);
                s_thri[1] = (uint32_t)(me & 0xFFFFu);
            }
        }
        __syncthreads();
    }

    const uint32_t thrkP = s_thrk[0], thriP = s_thri[0];
    const uint32_t thrkN = s_thrk[1], thriN = s_thri[1];

    // ---- final pass: selected BCE (mask from regs, key+cls from shared) ----
    float lcls = 0.f;
    #pragma unroll
    for (int j = 0; j < NITER; j++) {
        int i = tid + j * BLOCK;
        if (i >= A_TOT) break;
        int m = (mbits >> (2 * j)) & 3;
        if (m == 2) continue;
        uint32_t key = s_key[i];
        uint32_t tk = (m == 1) ? thrkP : thrkN;
        uint32_t ti = (m == 1) ? thriP : thriN;
        bool sel = (key < tk) || ((key == tk) && ((uint32_t)i <= ti));
        if (sel) {
            float c = s_cls[i];
            lcls += softplus_f((m == 1) ? -c : c);
        }
    }
    lcls = warpReduceSum(lcls);
    if ((tid & 31) == 0) atomicAdd(&s_clssum, lcls);
    __syncthreads();

    __shared__ bool s_last;
    if (tid == 0) {
        float denom = (float)max(k_p + k_n, 1);
        g_partial[n]            = s_clssum / denom;
        g_partial[NBLK + n]     = (npos > 0) ? (s_regsum / (4.0f * (float)npos)) : 0.0f;
        g_partial[2 * NBLK + n] = (float)naccc / (float)A_TOT;
        __threadfence();
        int prev = atomicAdd(&g_done, 1);
        s_last = (prev == NBLK - 1);
    }
    __syncthreads();

    // last block folds the final reduction — reuse s_cls as scratch (dead now)
    if (s_last) {
        float* sh0 = s_cls;            // [0, 128)
        float* sh1 = s_cls + BLOCK;    // [128, 256)
        float* sh2 = s_cls + 2*BLOCK;  // [256, 384)
        float lc = 0.f, lr = 0.f, acs = 0.f;
        for (int i = tid; i < NBLK; i += BLOCK) {
            lc  += g_partial[i];
            lr  += g_partial[NBLK + i];
            acs += g_partial[2 * NBLK + i];
        }
        __syncthreads();
        sh0[tid] = lc; sh1[tid] = lr; sh2[tid] = acs;
        __syncthreads();
        #pragma unroll
        for (int off = BLOCK / 2; off > 0; off >>= 1) {
            if (tid < off) {
                sh0[tid] += sh0[tid + off];
                sh1[tid] += sh1[tid + off];
                sh2[tid] += sh2[tid + off];
            }
            __syncthreads();
        }
        if (tid == 0) {
            float mlc = sh0[0] / (float)NBLK;
            float mlr = sh1[0] / (float)NBLK;
            float mac = sh2[0] / (float)NBLK;
            out[0] = mlc + mlr;
            out[1] = mlc;
            out[2] = mlr;
            out[3] = mac;
            g_done = 0;   // reset for next graph replay
        }
    }
}

extern "C" void kernel_launch(void* const* d_in, const int* in_sizes, int n_in,
                              void* d_out, int out_size) {
    const float* pred_cls      = (const float*)d_in[0];
    const float* pred_reg      = (const float*)d_in[1];
    const float* gt_bbox       = (const float*)d_in[2];
    const float* anchor_center = (const float*)d_in[3];
    const float* anchor_corner = (const float*)d_in[4];
    (void)in_sizes; (void)n_in; (void)out_size;

    rpn_sample_kernel<<<NBLK, BLOCK>>>(pred_cls, pred_reg, gt_bbox,
                                       anchor_center, anchor_corner,
                                       (float*)d_out);
}

// round 17
// speedup vs baseline: 1.1259x; 1.0497x over previous
#include <cuda_runtime.h>
#include <cstdint>

#define A_TOT 1445
#define NBLK 4096
#define BLOCK 128
#define NITER 12            // ceil(1445 / 128)
#define BUFCAP 128

__device__ float g_partial[3 * NBLK];
__device__ int g_done = 0;

__device__ __forceinline__ void tf_round(uint32_t &x0, uint32_t &x1, int r) {
    x0 += x1;
    x1 = __funnelshift_l(x1, x1, r);
    x1 ^= x0;
}

// JAX threefry2x32 (20 rounds)
__device__ __forceinline__ uint2 threefry2x32(uint32_t k0, uint32_t k1, uint32_t x0, uint32_t x1) {
    uint32_t k2 = k0 ^ k1 ^ 0x1BD11BDAu;
    x0 += k0; x1 += k1;
    tf_round(x0,x1,13); tf_round(x0,x1,15); tf_round(x0,x1,26); tf_round(x0,x1,6);
    x0 += k1; x1 += k2 + 1u;
    tf_round(x0,x1,17); tf_round(x0,x1,29); tf_round(x0,x1,16); tf_round(x0,x1,24);
    x0 += k2; x1 += k0 + 2u;
    tf_round(x0,x1,13); tf_round(x0,x1,15); tf_round(x0,x1,26); tf_round(x0,x1,6);
    x0 += k0; x1 += k1 + 3u;
    tf_round(x0,x1,17); tf_round(x0,x1,29); tf_round(x0,x1,16); tf_round(x0,x1,24);
    x0 += k1; x1 += k2 + 4u;
    tf_round(x0,x1,13); tf_round(x0,x1,15); tf_round(x0,x1,26); tf_round(x0,x1,6);
    x0 += k2; x1 += k0 + 5u;
    return make_uint2(x0, x1);
}

// two independent counters under the SAME key, interleaved for ILP
__device__ __forceinline__ void threefry2x32_pair_samekey(
    uint32_t k0, uint32_t k1, uint32_t xa, uint32_t xb,
    uint32_t &oa, uint32_t &ob)
{
    uint32_t k2 = k0 ^ k1 ^ 0x1BD11BDAu;
    uint32_t a0 = k0, a1 = xa + k1;
    uint32_t b0 = k0, b1 = xb + k1;
    #define TFP(r) { a0 += a1; a1 = __funnelshift_l(a1,a1,r); a1 ^= a0; \
                     b0 += b1; b1 = __funnelshift_l(b1,b1,r); b1 ^= b0; }
    TFP(13) TFP(15) TFP(26) TFP(6)
    a0 += k1; a1 += k2 + 1u;  b0 += k1; b1 += k2 + 1u;
    TFP(17) TFP(29) TFP(16) TFP(24)
    a0 += k2; a1 += k0 + 2u;  b0 += k2; b1 += k0 + 2u;
    TFP(13) TFP(15) TFP(26) TFP(6)
    a0 += k0; a1 += k1 + 3u;  b0 += k0; b1 += k1 + 3u;
    TFP(17) TFP(29) TFP(16) TFP(24)
    a0 += k1; a1 += k2 + 4u;  b0 += k1; b1 += k2 + 4u;
    TFP(13) TFP(15) TFP(26) TFP(6)
    a0 += k2; a1 += k0 + 5u;  b0 += k2; b1 += k0 + 5u;
    #undef TFP
    oa = a0 ^ a1;
    ob = b0 ^ b1;
}

__device__ __forceinline__ float softplus_f(float x) {
    return fmaxf(x, 0.0f) + log1pf(expf(-fabsf(x)));
}

__device__ __forceinline__ float warpReduceSum(float v) {
    #pragma unroll
    for (int o = 16; o > 0; o >>= 1) v += __shfl_down_sync(0xffffffffu, v, o);
    return v;
}

__global__ __launch_bounds__(BLOCK, 16) void rpn_sample_kernel(
    const float* __restrict__ pred_cls,
    const float* __restrict__ pred_reg,
    const float* __restrict__ gt_bbox,
    const float* __restrict__ anchor_center,
    const float* __restrict__ anchor_corner,
    float* __restrict__ out)
{
    __shared__ float s_cls[A_TOT];             // logits; reused as reduce scratch at end
    __shared__ uint32_t s_key[A_TOT];          // 23-bit uniform key (bits >> 9)
    __shared__ int s_hist[256];
    __shared__ unsigned long long s_buf[BUFCAP];
    __shared__ int s_cnt[4];                   // npos, nneg, acc, bufcnt
    __shared__ float s_regsum;
    __shared__ float s_clssum;
    __shared__ uint32_t s_thrk[2], s_thri[2];  // thresholds: key + index
    __shared__ int s_bin, s_cumb;

    const int n = blockIdx.x;
    const int tid = threadIdx.x;

    // zero histogram + control state before any use
    s_hist[tid] = 0;
    s_hist[tid + BLOCK] = 0;
    if (tid == 0) {
        s_regsum = 0.f; s_clssum = 0.f;
        s_cnt[0] = s_cnt[1] = s_cnt[2] = s_cnt[3] = 0;
        s_thrk[0] = 0xFFFFFFFFu; s_thri[0] = 0xFFFFFFFFu;
        s_thrk[1] = 0xFFFFFFFFu; s_thri[1] = 0xFFFFFFFFu;
    }

    // neg-stream key only (pos keys needed only if npos > 16 — computed lazily)
    uint32_t kn0, kn1;
    {
        uint2 kn = threefry2x32(0u, 42u, 0u, (uint32_t)(NBLK + n));
        kn0 = kn.x; kn1 = kn.y;
    }
    __syncthreads();   // hist/cnt zero visible before fused-loop atomics

    const float4 gt = __ldg(((const float4*)gt_bbox) + n);
    const float ga = __fmul_rn(__fsub_rn(gt.z, gt.x), __fsub_rn(gt.w, gt.y));
    const float gcx = (gt.x + gt.z) * 0.5f;
    const float gcy = (gt.y + gt.w) * 0.5f;
    const float gw = gt.z - gt.x, gh = gt.w - gt.y;

    const float* pc = pred_cls + (size_t)n * A_TOT;
    const float* prg = pred_reg + (size_t)n * 4 * A_TOT;

    int lcnt = 0;          // packed per-warp: lpos<<20 | lneg<<10 | lacc
    float lreg = 0.f;
    uint32_t mbits = 0;    // 2 bits per j: this thread's anchor masks

    // ---- fused loop: loads -> cipher (in load shadow) -> IoU -> hist ----
    for (int t = 0; t < 6; t++) {
        const int j1 = 2 * t, j2 = 2 * t + 1;
        const int i1 = tid + j1 * BLOCK;
        const int i2 = tid + j2 * BLOCK;
        const bool v2 = (i2 < A_TOT);   // only last pair is partial (i1 always valid)

        // issue loads first — consumed after the cipher
        float4 ac1 = __ldg(((const float4*)anchor_corner) + i1);
        float4 ac2 = __ldg(((const float4*)anchor_corner) + (v2 ? i2 : i1));
        float c1 = __ldg(pc + i1);
        float c2 = __ldg(pc + (v2 ? i2 : i1));

        // ~100 ALU instructions fill the load latency shadow
        uint32_t ya, yb;
        threefry2x32_pair_samekey(kn0, kn1, (uint32_t)i1, (uint32_t)i2, ya, yb);
        uint32_t ka = ya >> 9, kb = yb >> 9;
        s_key[i1] = ka;
        if (v2) s_key[i2] = kb;

        // IoU + mask, anchor 1
        {
            float ltx = fmaxf(gt.x, ac1.x), lty = fmaxf(gt.y, ac1.y);
            float rbx = fminf(gt.z, ac1.z), rby = fminf(gt.w, ac1.w);
            float w = fmaxf(__fsub_rn(rbx, ltx), 0.f);
            float h = fmaxf(__fsub_rn(rby, lty), 0.f);
            float inter = __fmul_rn(w, h);
            float ab = __fmul_rn(__fsub_rn(ac1.z, ac1.x), __fsub_rn(ac1.w, ac1.y));
            float uni = __fsub_rn(__fadd_rn(ga, ab), inter);
            float iou = __fdiv_rn(inter, uni);
            int m = (iou > 0.6f) ? 1 : ((iou < 0.3f) ? 0 : 2);
            mbits |= (uint32_t)m << (2 * j1);
            s_cls[i1] = c1;
            bool pos = (m == 1);
            lcnt += ((c1 >= 0.6f) == pos) ? 1 : 0;
            lcnt += pos ? 0x100000 : ((m == 0) ? 0x400 : 0);
            if (m == 0) atomicAdd(&s_hist[ka >> 15], 1);
            if (pos) {
                float4 ce = __ldg(((const float4*)anchor_center) + i1);
                float t0 = (gcx - ce.x) / ce.z;
                float t1 = (gcy - ce.y) / ce.w;
                float t2 = logf(gw / ce.z);
                float t3 = logf(gh / ce.w);
                float d0 = prg[i1]             - t0;
                float d1 = prg[A_TOT + i1]     - t1;
                float d2 = prg[2 * A_TOT + i1] - t2;
                float d3 = prg[3 * A_TOT + i1] - t3;
                lreg += d0 * d0 + d1 * d1 + d2 * d2 + d3 * d3;
            }
        }

        // IoU + mask, anchor 2
        if (v2) {
            float ltx = fmaxf(gt.x, ac2.x), lty = fmaxf(gt.y, ac2.y);
            float rbx = fminf(gt.z, ac2.z), rby = fminf(gt.w, ac2.w);
            float w = fmaxf(__fsub_rn(rbx, ltx), 0.f);
            float h = fmaxf(__fsub_rn(rby, lty), 0.f);
            float inter = __fmul_rn(w, h);
            float ab = __fmul_rn(__fsub_rn(ac2.z, ac2.x), __fsub_rn(ac2.w, ac2.y));
            float uni = __fsub_rn(__fadd_rn(ga, ab), inter);
            float iou = __fdiv_rn(inter, uni);
            int m = (iou > 0.6f) ? 1 : ((iou < 0.3f) ? 0 : 2);
            mbits |= (uint32_t)m << (2 * j2);
            s_cls[i2] = c2;
            bool pos = (m == 1);
            lcnt += ((c2 >= 0.6f) == pos) ? 1 : 0;
            lcnt += pos ? 0x100000 : ((m == 0) ? 0x400 : 0);
            if (m == 0) atomicAdd(&s_hist[kb >> 15], 1);
            if (pos) {
                float4 ce = __ldg(((const float4*)anchor_center) + i2);
                float t0 = (gcx - ce.x) / ce.z;
                float t1 = (gcy - ce.y) / ce.w;
                float t2 = logf(gw / ce.z);
                float t3 = logf(gh / ce.w);
                float d0 = prg[i2]             - t0;
                float d1 = prg[A_TOT + i2]     - t1;
                float d2 = prg[2 * A_TOT + i2] - t2;
                float d3 = prg[3 * A_TOT + i2] - t3;
                lreg += d0 * d0 + d1 * d1 + d2 * d2 + d3 * d3;
            }
        }
    }

    // warp-level packed sum is safe (<= 384 per field); unpack before block atomics
    lcnt = (int)__reduce_add_sync(0xffffffffu, (unsigned)lcnt);
    lreg = warpReduceSum(lreg);
    if ((tid & 31) == 0) {
        atomicAdd(&s_cnt[0], lcnt >> 20);
        atomicAdd(&s_cnt[1], (lcnt >> 10) & 0x3FF);
        atomicAdd(&s_cnt[2], lcnt & 0x3FF);
        atomicAdd(&s_regsum, lreg);
    }
    __syncthreads();

    const int npos = s_cnt[0], nneg = s_cnt[1], naccc = s_cnt[2];
    const int k_p = min(npos, 16);
    const int k_n = min(nneg, (npos > 0) ? 3 * npos : 48);

    // ---- positive threshold (rare: npos > 16): lazily compute kp ciphers ----
    if (npos > k_p) {
        uint32_t kp0, kp1;
        {
            uint2 kp = threefry2x32(0u, 42u, 0u, (uint32_t)n);
            kp0 = kp.x; kp1 = kp.y;
        }
        if (tid == 0) s_cnt[3] = 0;
        __syncthreads();
        #pragma unroll
        for (int j = 0; j < NITER; j++) {
            int i = tid + j * BLOCK;
            if (i < A_TOT && ((mbits >> (2 * j)) & 3) == 1) {
                uint2 y = threefry2x32(kp0, kp1, 0u, (uint32_t)i);
                uint32_t key = (y.x ^ y.y) >> 9;
                s_key[i] = key;   // pos entries now carry kp keys
                int p = atomicAdd(&s_cnt[3], 1);
                if (p < BUFCAP) s_buf[p] = (((unsigned long long)key) << 16) | (unsigned)i;
            }
        }
        __syncthreads();
        int m = min(s_cnt[3], BUFCAP);
        for (int t = tid; t < m; t += BLOCK) {
            unsigned long long me = s_buf[t];
            int cnt = 0;
            for (int q = 0; q < m; q++) cnt += (s_buf[q] < me) ? 1 : 0;
            if (cnt == k_p - 1) {
                s_thrk[0] = (uint32_t)(me >> 16);
                s_thri[0] = (uint32_t)(me & 0xFFFFu);
            }
        }
        __syncthreads();
        if (tid == 0) s_cnt[3] = 0;
        __syncthreads();
    }

    // ---- negative threshold: histogram scan + in-bin rank ----
    if (nneg > k_n) {
        if (tid < 32) {
            int base = tid * 8;
            int h[8];
            int lsum = 0;
            #pragma unroll
            for (int j = 0; j < 8; j++) { h[j] = s_hist[base + j]; lsum += h[j]; }
            int incl = lsum;
            #pragma unroll
            for (int o = 1; o < 32; o <<= 1) {
                int t = __shfl_up_sync(0xffffffffu, incl, o);
                if (tid >= o) incl += t;
            }
            int run = incl - lsum;
            #pragma unroll
            for (int j = 0; j < 8; j++) {
                int nrun = run + h[j];
                if (run < k_n && k_n <= nrun) { s_bin = base + j; s_cumb = run; }
                run = nrun;
            }
        }
        __syncthreads();
        const int bin = s_bin, cumb = s_cumb;
        #pragma unroll
        for (int j = 0; j < NITER; j++) {
            int i = tid + j * BLOCK;
            if (i < A_TOT && ((mbits >> (2 * j)) & 3) == 0) {
                uint32_t key = s_key[i];
                if ((int)(key >> 15) == bin) {
                    int p = atomicAdd(&s_cnt[3], 1);
                    if (p < BUFCAP) s_buf[p] = (((unsigned long long)key) << 16) | (unsigned)i;
                }
            }
        }
        __syncthreads();
        int m = min(s_cnt[3], BUFCAP);
        int j = k_n - cumb;   // 1-indexed rank within bin
        for (int t = tid; t < m; t += BLOCK) {
            unsigned long long me = s_buf[t];
            int cnt = 0;
            for (int q = 0; q < m; q++) cnt += (s_buf[q] < me) ? 1 : 0;
            if (cnt == j - 1) {
                s_thrk[1] = (uint32_t)(me >> 16);
                s_thri[1] = (uint32_t)(me & 0xFFFFu);
            }
        }
        __syncthreads();
    }

    const uint32_t thrkP = s_thrk[0], thriP = s_thri[0];
    const uint32_t thrkN = s_thrk[1], thriN = s_thri[1];

    // ---- final pass: selected BCE (mask from regs, key+cls from shared) ----
    float lcls = 0.f;
    #pragma unroll
    for (int j = 0; j < NITER; j++) {
        int i = tid + j * BLOCK;
        if (i >= A_TOT) break;
        int m = (mbits >> (2 * j)) & 3;
        if (m == 2) continue;
        uint32_t key = s_key[i];
        uint32_t tk = (m == 1) ? thrkP : thrkN;
        uint32_t ti = (m == 1) ? thriP : thriN;
        bool sel = (key < tk) || ((key == tk) && ((uint32_t)i <= ti));
        if (sel) {
            float c = s_cls[i];
            lcls += softplus_f((m == 1) ? -c : c);
        }
    }
    lcls = warpReduceSum(lcls);
    if ((tid & 31) == 0) atomicAdd(&s_clssum, lcls);
    __syncthreads();

    __shared__ bool s_last;
    if (tid == 0) {
        float denom = (float)max(k_p + k_n, 1);
        g_partial[n]            = s_clssum / denom;
        g_partial[NBLK + n]     = (npos > 0) ? (s_regsum / (4.0f * (float)npos)) : 0.0f;
        g_partial[2 * NBLK + n] = (float)naccc / (float)A_TOT;
        __threadfence();
        int prev = atomicAdd(&g_done, 1);
        s_last = (prev == NBLK - 1);
    }
    __syncthreads();

    // last block folds the final reduction — reuse s_cls as scratch (dead now)
    if (s_last) {
        float* sh0 = s_cls;            // [0, 128)
        float* sh1 = s_cls + BLOCK;    // [128, 256)
        float* sh2 = s_cls + 2*BLOCK;  // [256, 384)
        float lc = 0.f, lr = 0.f, acs = 0.f;
        for (int i = tid; i < NBLK; i += BLOCK) {
            lc  += g_partial[i];
            lr  += g_partial[NBLK + i];
            acs += g_partial[2 * NBLK + i];
        }
        __syncthreads();
        sh0[tid] = lc; sh1[tid] = lr; sh2[tid] = acs;
        __syncthreads();
        #pragma unroll
        for (int off = BLOCK / 2; off > 0; off >>= 1) {
            if (tid < off) {
                sh0[tid] += sh0[tid + off];
                sh1[tid] += sh1[tid + off];
                sh2[tid] += sh2[tid + off];
            }
            __syncthreads();
        }
        if (tid == 0) {
            float mlc = sh0[0] / (float)NBLK;
            float mlr = sh1[0] / (float)NBLK;
            float mac = sh2[0] / (float)NBLK;
            out[0] = mlc + mlr;
            out[1] = mlc;
            out[2] = mlr;
            out[3] = mac;
            g_done = 0;   // reset for next graph replay
        }
    }
}

extern "C" void kernel_launch(void* const* d_in, const int* in_sizes, int n_in,
                              void* d_out, int out_size) {
    const float* pred_cls      = (const float*)d_in[0];
    const float* pred_reg      = (const float*)d_in[1];
    const float* gt_bbox       = (const float*)d_in[2];
    const float* anchor_center = (const float*)d_in[3];
    const float* anchor_corner = (const float*)d_in[4];
    (void)in_sizes; (void)n_in; (void)out_size;

    rpn_sample_kernel<<<NBLK, BLOCK>>>(pred_cls, pred_reg, gt_bbox,
                                       anchor_center, anchor_corner,
                                       (float*)d_out);
}